// round 15
// baseline (speedup 1.0000x reference)
#include <cuda_runtime.h>

static constexpr int NV   = 48;
static constexpr int NP1  = 49;
static constexpr int NB   = 98;
static constexpr int NSEG = 65536;
static constexpr int RPB  = 8;     // rows per block (8 warps, 256 threads)
static constexpr int HE   = 8;     // hash windows per warp

static constexpr float PW0 = 0.01f;
static constexpr float PW1 = 0.005f;

// self-cleaning accumulator (zero-initialized; every launch restores 0/0)
__device__ float    g_accum = 0.f;
__device__ unsigned g_ctr   = 0u;

struct __align__(16) RowS {
    float4 tbl[NB + 1];     // {bounds, cdf, Bq, Gq}; tbl[NB].x = +inf sentinel
    float sd[NP1];
    float wn[NV];
    float bounds[NB + 1];   // scalar copy for search + scans (+inf sentinel)
    float rs[NB];
    float wb[NB];
    float cdf[NB];
};

__device__ __forceinline__ float warpsum(float v) {
    #pragma unroll
    for (int o = 16; o; o >>= 1) v += __shfl_xor_sync(0xffffffffu, v, o);
    return v;
}

__device__ __forceinline__ float warp_excl_from_total(float tot, int lane) {
    float inc = tot;
    #pragma unroll
    for (int o = 1; o < 32; o <<= 1) {
        float y = __shfl_up_sync(0xffffffffu, inc, o);
        if (lane >= o) inc += y;
    }
    return inc - tot;
}

// interp: lane owns contiguous chunk of CH diffs; carried float4 registers make the
// eval load-free: res(x) = t0.y + num*(t0.z + num*t0.w), num = x - t0.x; 0 for k<0
template <int CH>
__device__ __forceinline__ float interp_chunk(RowS& S, const float* __restrict__ psd,
                                              const float* __restrict__ pwt,
                                              int row, int XP, int lane, float scale)
{
    const int c0 = lane * CH;
    const float* px = psd + row * XP + c0;
    const float* pv = pwt + row * (XP - 1) + c0;

    float x = px[0];
    int lo = 0, hi = NB;
    #pragma unroll
    for (int st = 0; st < 7; ++st) {
        if (lo < hi) {
            int mid = (lo + hi) >> 1;
            if (S.bounds[mid] <= x) lo = mid + 1; else hi = mid;
        }
    }
    int k = lo - 1;
    float4 t0 = S.tbl[k < 0 ? 0 : k];
    float4 t1 = S.tbl[k + 1];          // tbl[NB].x = +inf sentinel

    float lsum = 0.f, resprev = 0.f;
    #pragma unroll
    for (int j = 0; j <= CH; ++j) {
        if (j > 0) {
            x = px[j];
            while (t1.x <= x) { ++k; t0 = t1; t1 = S.tbl[k + 1]; }
        }
        float res = 0.f;
        if (k >= 0) {
            float num = x - t0.x;
            res = fmaf(num, fmaf(num, t0.w, t0.z), t0.y);
        }
        if (j > 0) {
            float ws  = res - resprev;
            float pwv = pv[j - 1];
            float d = ws - pwv;
            if (d > 0.f) lsum += d * d * __fdividef(1.f, pwv + 1e-5f);
        }
        resprev = res;
    }
    return lsum * scale;
}

__global__ __launch_bounds__(RPB * 32)
void mega_kernel(const float* __restrict__ pd, const float* __restrict__ gt,
                 const float* __restrict__ rsd, const float* __restrict__ rw,
                 const float* __restrict__ psd0, const float* __restrict__ pwt0,
                 const float* __restrict__ psd1, const float* __restrict__ pwt1,
                 const float* __restrict__ emb0, const float* __restrict__ emb1,
                 const int* __restrict__ idx0, const int* __restrict__ idx1,
                 float* __restrict__ out, int R, int XP0, int XP1, int M,
                 int ROWB, int HBL)
{
    __shared__ RowS sm[RPB];
    __shared__ float bacc[RPB];

    const int warp = threadIdx.x >> 5;
    const int lane = threadIdx.x & 31;

    if (blockIdx.x >= (unsigned)ROWB) {
        // ================= hash role: run-ownership, no scratch =================
        int h     = blockIdx.x - ROWB;
        int level = h / HBL;
        int bh    = h % HBL;
        const float* emb = level ? emb1 : emb0;
        const int*   idx = level ? idx1 : idx0;
        const float hscale = 0.1f / (2.f * (float)NSEG);

        float acc = 0.f;
        const int warpbase = (bh * RPB + warp) * (32 * HE);
        #pragma unroll 1
        for (int e = 0; e < HE; ++e) {
            int b = warpbase + e * 32;
            if (b >= M) break;
            int i = b + lane;
            bool ok = i < M;
            int s = ok ? idx[i] : -1;
            float v = 0.f;
            if (ok) {
                float2 e2 = ((const float2*)emb)[i];
                v = e2.x * e2.x + e2.y * e2.y;
            }
            int prev = -2;
            if (lane == 0 && b > 0) prev = idx[b - 1];
            prev = __shfl_sync(0xffffffffu, prev, 0);

            unsigned m = __match_any_sync(0xffffffffu, s);
            int leader = __ffs(m) - 1;
            int hib = 31 - __clz(m);
            #pragma unroll
            for (int o = 16; o; o >>= 1) {
                float y = __shfl_down_sync(0xffffffffu, v, o);
                if (lane + o <= hib) v += y;
            }
            if (ok && lane == leader && !(leader == 0 && s == prev)) {
                int cnt = __popc(m);
                if (hib == 31) {                  // run extends past window
                    int j = b + 32;
                    while (j < M && idx[j] == s) {
                        float2 e2 = ((const float2*)emb)[j];
                        v += e2.x * e2.x + e2.y * e2.y;
                        ++cnt; ++j;
                    }
                }
                acc += __fdividef(v, (float)cnt);
            }
        }
        float wsum = warpsum(acc * hscale);
        if (lane == 0) bacc[warp] = wsum;
    } else {
        // ================= row role =================
        const int row = blockIdx.x * RPB + warp;
        float acc = 0.f;

        {
            RowS& S = sm[warp];

            for (int i = lane; i < NP1; i += 32) S.sd[i] = rsd[row * NP1 + i];
            __syncwarp();
            for (int i = lane; i < NV; i += 32) {
                float wv = rw[row * NV + i];
                S.wn[i] = wv * __fdividef(1.f, S.sd[i + 1] - S.sd[i] + 1e-8f);
            }

            if (lane < 3) {
                float d = pd[row * 3 + lane] - gt[row * 3 + lane];
                acc += d * d * (1.f / (3.f * 4096.f));
            }

            // ---- distortion via prefix sums (mid sorted; abs of nonneg sums = no-op) ----
            {
                float w0 = 0.f, w1 = 0.f, m0 = 0.f, m1 = 0.f, d0 = 0.f, d1 = 0.f;
                if (lane < 24) {
                    float2 wv = ((const float2*)(rw + row * NV))[lane];
                    w0 = wv.x; w1 = wv.y;
                    int n0 = 2 * lane;
                    float s0 = S.sd[n0], s1 = S.sd[n0 + 1], s2 = S.sd[n0 + 2];
                    m0 = 0.5f * (s0 + s1);
                    m1 = 0.5f * (s1 + s2);
                    d0 = s1 - s0;
                    d1 = s2 - s1;
                }
                float sw  = w0 + w1;
                float swm = w0 * m0 + w1 * m1;
                float cA = warp_excl_from_total(sw, lane);
                float cB = warp_excl_from_total(swm, lane);
                float p1 = 2.f * (w0 * (m0 * cA - cB)
                               + w1 * (m1 * (cA + w0) - (cB + w0 * m0)));
                float p2 = w0 * w0 * d0 + w1 * w1 * d1;
                acc += (p1 + p2 * (1.f / 3.f)) * (0.01f / 4096.f);
            }
            __syncwarp();

            #pragma unroll 1
            for (int lev = 0; lev < 2; ++lev) {
                const float pw = lev ? PW1 : PW0;
                const float inv2pw = lev ? (1.f / (2.f * PW1)) : (1.f / (2.f * PW0));
                const float* psd = lev ? psd1 : psd0;
                const float* pwt = lev ? pwt1 : pwt0;
                const int XP = lev ? XP1 : XP0;
                const float scale = 1.f / ((float)R * (float)(XP - 1));

                // ---- specialized stable merge (rank-scatter) ----
                {
                    const bool low1 = lane < 17;
                    const bool ok3  = lane < 2;
                    const int  j1   = low1 ? lane + 32 : lane - 17;
                    const int  j2   = lane + 15;
                    const int  j3   = lane + 47;

                    float val0 = S.sd[lane] - pw;
                    float val1 = low1 ? S.sd[j1] - pw : S.sd[j1] + pw;
                    float val2 = S.sd[j2] + pw;
                    float val3 = ok3 ? S.sd[j3] + pw : 0.f;

                    int lo0 = 0, hi0 = NP1, lo1 = 0, hi1 = NP1;
                    int lo2 = 0, hi2 = NP1, lo3 = 0, hi3 = NP1;
                    #pragma unroll
                    for (int s = 0; s < 6; ++s) {
                        if (lo0 < hi0) {
                            int mid = (lo0 + hi0) >> 1;
                            if (S.sd[mid] + pw < val0) lo0 = mid + 1; else hi0 = mid;
                        }
                        if (lo1 < hi1) {
                            int mid = (lo1 + hi1) >> 1;
                            float sv = S.sd[mid];
                            bool adv = low1 ? (sv + pw < val1) : (sv - pw <= val1);
                            if (adv) lo1 = mid + 1; else hi1 = mid;
                        }
                        if (lo2 < hi2) {
                            int mid = (lo2 + hi2) >> 1;
                            if (S.sd[mid] - pw <= val2) lo2 = mid + 1; else hi2 = mid;
                        }
                        if (ok3 && lo3 < hi3) {
                            int mid = (lo3 + hi3) >> 1;
                            if (S.sd[mid] - pw <= val3) lo3 = mid + 1; else hi3 = mid;
                        }
                    }
                    {
                        float dd = S.wn[lane] - (lane > 0 ? S.wn[lane - 1] : 0.f);
                        int pos = lane + lo0;
                        S.bounds[pos] = val0;
                        S.rs[pos] = dd * inv2pw;
                    }
                    {
                        float dd = (j1 < NV ? S.wn[j1] : 0.f) - (j1 > 0 ? S.wn[j1 - 1] : 0.f);
                        float rv = (low1 ? dd : -dd) * inv2pw;
                        int pos = j1 + lo1;
                        S.bounds[pos] = val1;
                        S.rs[pos] = rv;
                    }
                    {
                        float dd = S.wn[j2] - S.wn[j2 - 1];
                        int pos = j2 + lo2;
                        S.bounds[pos] = val2;
                        S.rs[pos] = -dd * inv2pw;
                    }
                    if (ok3) {
                        float dd = (j3 < NV ? S.wn[j3] : 0.f) - S.wn[j3 - 1];
                        int pos = j3 + lo3;
                        S.bounds[pos] = val3;
                        S.rs[pos] = -dd * inv2pw;
                    }
                    if (lane == 0) S.bounds[NB] = __int_as_float(0x7f800000); // +inf
                }
                __syncwarp();

                // three blocked scans over 97 elements
                const int base = lane * 4;
                float r4[4], ds4[4];
                #pragma unroll
                for (int t = 0; t < 4; ++t) {
                    int k = base + t;
                    bool v = (k < NB - 1);
                    r4[t]  = v ? S.rs[k] : 0.f;
                    ds4[t] = v ? (S.bounds[k + 1] - S.bounds[k]) : 0.f;
                }
                float c = 0.f, cum4[4];
                #pragma unroll
                for (int t = 0; t < 4; ++t) { c += r4[t]; cum4[t] = c; }
                float carry1 = warp_excl_from_total(c, lane);
                float c2 = 0.f, rec4[4];
                #pragma unroll
                for (int t = 0; t < 4; ++t) { c2 += ds4[t] * (cum4[t] + carry1); rec4[t] = c2; }
                float carry2 = warp_excl_from_total(c2, lane);
                float c3 = 0.f, cdf4[4], wb4[4];
                float wprev = (base == 0) ? 0.f : fmaxf(carry2, 0.f);
                #pragma unroll
                for (int t = 0; t < 4; ++t) {
                    float wbk1 = fmaxf(rec4[t] + carry2, 0.f);
                    wb4[t] = wbk1;
                    c3 += 0.5f * (wbk1 + wprev) * ds4[t];
                    cdf4[t] = c3;
                    wprev = wbk1;
                }
                float carry3 = warp_excl_from_total(c3, lane);
                #pragma unroll
                for (int t = 0; t < 4; ++t) {
                    int k = base + t;
                    if (k < NB - 1) {
                        S.wb[k + 1]  = wb4[t];
                        S.cdf[k + 1] = cdf4[t] + carry3;
                    }
                }
                if (lane == 0) { S.wb[0] = 0.f; S.cdf[0] = 0.f; }
                __syncwarp();

                // ---- build packed quadratic table tbl[k] = {bounds, cdf, Bq, Gq} ----
                {
                    int run = -1, loc[4];
                    #pragma unroll
                    for (int t = 0; t < 4; ++t) {
                        int k = base + t;
                        int gk = -1;
                        if (k == 0) gk = 0;
                        else if (k < NB) gk = (S.cdf[k] != S.cdf[k - 1]) ? k : -1;
                        run = max(run, gk);
                        loc[t] = run;
                    }
                    int inc = run;
                    #pragma unroll
                    for (int o = 1; o < 32; o <<= 1) {
                        int y = __shfl_up_sync(0xffffffffu, inc, o);
                        if (lane >= o) inc = max(inc, y);
                    }
                    int excl = __shfl_up_sync(0xffffffffu, inc, 1);
                    if (lane == 0) excl = -1;
                    const float cdfN = S.cdf[NB - 1];
                    #pragma unroll
                    for (int t = 0; t < 4; ++t) {
                        int k = base + t;
                        if (k < NB) {
                            int ieq = max(loc[t], excl);
                            float wbeqk = S.wb[ieq];
                            float bk = S.bounds[k];
                            float ck = S.cdf[k];
                            float Bqv, Gqv;
                            if (k < NB - 1) {
                                float den  = S.bounds[k + 1] - bk;
                                float fp1e = (S.cdf[k + 1] == cdfN) ? 0.f : S.wb[k + 1];
                                Bqv = wbeqk;
                                Gqv = 0.5f * (fp1e - wbeqk) * __fdividef(1.f, den);
                            } else {
                                Bqv = 0.5f * wbeqk;   // k = NB-1 tail: off = (num>0)
                                Gqv = 0.f;
                            }
                            S.tbl[k] = make_float4(bk, ck, Bqv, Gqv);
                        }
                    }
                    if (lane == 0)
                        S.tbl[NB] = make_float4(__int_as_float(0x7f800000), 0.f, 0.f, 0.f);
                }
                __syncwarp();

                if (lev == 0) acc += interp_chunk<8>(S, psd, pwt, row, XP, lane, scale);
                else          acc += interp_chunk<3>(S, psd, pwt, row, XP, lane, scale);
                __syncwarp();
            }
        }

        float wa = warpsum(acc);
        if (lane == 0) bacc[warp] = wa;
    }

    // ===== tail: block sum -> global accum -> last block writes out =====
    __syncthreads();
    if (threadIdx.x == 0) {
        float t = 0.f;
        #pragma unroll
        for (int i = 0; i < RPB; ++i) t += bacc[i];
        atomicAdd(&g_accum, t);
        __threadfence();
        unsigned old = atomicAdd(&g_ctr, 1u);
        if (old == gridDim.x - 1) {
            float r = atomicExch(&g_accum, 0.f);
            out[0] = r;
            atomicExch(&g_ctr, 0u);
        }
    }
}

extern "C" void kernel_launch(void* const* d_in, const int* in_sizes, int n_in,
                              void* d_out, int out_size)
{
    const float* pd   = (const float*)d_in[0];
    const float* gt   = (const float*)d_in[1];
    const float* rsd  = (const float*)d_in[2];
    const float* rw   = (const float*)d_in[3];
    const float* psd0 = (const float*)d_in[4];
    const float* pwt0 = (const float*)d_in[5];
    const float* psd1 = (const float*)d_in[6];
    const float* pwt1 = (const float*)d_in[7];
    const float* emb0 = (const float*)d_in[8];
    const float* emb1 = (const float*)d_in[9];
    const int*   idx0 = (const int*)d_in[10];
    const int*   idx1 = (const int*)d_in[11];
    float* out = (float*)d_out;

    const int R   = in_sizes[0] / 3;
    const int XP0 = in_sizes[4] / R;
    const int XP1 = in_sizes[6] / R;
    const int M   = in_sizes[8] / 2;

    const int ROWB = (R + RPB - 1) / RPB;                        // 512
    const int HBL  = (M + RPB * 32 * HE - 1) / (RPB * 32 * HE);  // 96 per level

    mega_kernel<<<ROWB + 2 * HBL, RPB * 32>>>(pd, gt, rsd, rw,
                                              psd0, pwt0, psd1, pwt1,
                                              emb0, emb1, idx0, idx1,
                                              out, R, XP0, XP1, M, ROWB, HBL);
}

// round 16
// speedup vs baseline: 1.0986x; 1.0986x over previous
#include <cuda_runtime.h>

static constexpr int NV   = 48;
static constexpr int NP1  = 49;
static constexpr int NB   = 98;
static constexpr int NSEG = 65536;
static constexpr int RPB  = 8;     // rows per block (8 warps, 256 threads)
static constexpr int HE   = 8;     // hash windows per warp

static constexpr float PW0 = 0.01f;
static constexpr float PW1 = 0.005f;

// self-cleaning accumulator (zero-initialized; every launch restores 0/0)
__device__ float    g_accum = 0.f;
__device__ unsigned g_ctr   = 0u;

struct RowS {
    float sd[NP1];
    float wn[NV];
    float bounds[NB + 1];   // +1: sentinel = +inf
    float rs[NB];
    float wb[NB];
    float cdf[NB];
    float Bq[NB];           // quadratic coeff: linear term (== wb; 0.5*wb at tail)
    float Gq[NB];           // quadratic coeff: quadratic term
};

__device__ __forceinline__ float warpsum(float v) {
    #pragma unroll
    for (int o = 16; o; o >>= 1) v += __shfl_xor_sync(0xffffffffu, v, o);
    return v;
}

__device__ __forceinline__ float warp_excl_from_total(float tot, int lane) {
    float inc = tot;
    #pragma unroll
    for (int o = 1; o < 32; o <<= 1) {
        float y = __shfl_up_sync(0xffffffffu, inc, o);
        if (lane >= o) inc += y;
    }
    return inc - tot;
}

// interp: lane owns contiguous chunk of CH diffs; quadratic-table eval
// res(x) = cdf[k] + num*(Bq[k] + num*Gq[k]),  num = x - bounds[k];  res = 0 for k<0
template <int CH>
__device__ __forceinline__ float interp_chunk(RowS& S, const float* __restrict__ psd,
                                              const float* __restrict__ pwt,
                                              int row, int XP, int lane, float scale)
{
    const int c0 = lane * CH;
    const float* px = psd + row * XP + c0;
    const float* pv = pwt + row * (XP - 1) + c0;

    float x = px[0];
    int lo = 0, hi = NB;
    #pragma unroll
    for (int st = 0; st < 7; ++st) {
        if (lo < hi) {
            int mid = (lo + hi) >> 1;
            if (S.bounds[mid] <= x) lo = mid + 1; else hi = mid;
        }
    }
    int k = lo - 1;
    float b0 = S.bounds[k < 0 ? 0 : k];
    float b1 = S.bounds[k + 1];          // bounds[NB] = +inf sentinel

    float lsum = 0.f, resprev = 0.f;
    #pragma unroll
    for (int j = 0; j <= CH; ++j) {
        if (j > 0) {
            x = px[j];
            while (b1 <= x) { ++k; b0 = b1; b1 = S.bounds[k + 1]; }
        }
        float res = 0.f;
        if (k >= 0) {
            float num = x - b0;
            res = fmaf(num, fmaf(num, S.Gq[k], S.Bq[k]), S.cdf[k]);
        }
        if (j > 0) {
            float ws  = res - resprev;
            float pwv = pv[j - 1];
            float d = ws - pwv;
            if (d > 0.f) lsum += d * d * __fdividef(1.f, pwv + 1e-5f);
        }
        resprev = res;
    }
    return lsum * scale;
}

__global__ __launch_bounds__(RPB * 32)
void mega_kernel(const float* __restrict__ pd, const float* __restrict__ gt,
                 const float* __restrict__ rsd, const float* __restrict__ rw,
                 const float* __restrict__ psd0, const float* __restrict__ pwt0,
                 const float* __restrict__ psd1, const float* __restrict__ pwt1,
                 const float* __restrict__ emb0, const float* __restrict__ emb1,
                 const int* __restrict__ idx0, const int* __restrict__ idx1,
                 float* __restrict__ out, int R, int XP0, int XP1, int M,
                 int ROWB, int HBL)
{
    __shared__ RowS sm[RPB];
    __shared__ float bacc[RPB];

    const int warp = threadIdx.x >> 5;
    const int lane = threadIdx.x & 31;

    if (blockIdx.x >= (unsigned)ROWB) {
        // ================= hash role: run-ownership, no scratch =================
        int h     = blockIdx.x - ROWB;
        int level = h / HBL;
        int bh    = h % HBL;
        const float* emb = level ? emb1 : emb0;
        const int*   idx = level ? idx1 : idx0;
        const float hscale = 0.1f / (2.f * (float)NSEG);

        float acc = 0.f;
        const int warpbase = (bh * RPB + warp) * (32 * HE);
        #pragma unroll 1
        for (int e = 0; e < HE; ++e) {
            int b = warpbase + e * 32;
            if (b >= M) break;
            int i = b + lane;
            bool ok = i < M;
            int s = ok ? idx[i] : -1;
            float v = 0.f;
            if (ok) {
                float2 e2 = ((const float2*)emb)[i];
                v = e2.x * e2.x + e2.y * e2.y;
            }
            int prev = -2;
            if (lane == 0 && b > 0) prev = idx[b - 1];
            prev = __shfl_sync(0xffffffffu, prev, 0);

            unsigned m = __match_any_sync(0xffffffffu, s);
            int leader = __ffs(m) - 1;
            int hib = 31 - __clz(m);
            #pragma unroll
            for (int o = 16; o; o >>= 1) {
                float y = __shfl_down_sync(0xffffffffu, v, o);
                if (lane + o <= hib) v += y;
            }
            if (ok && lane == leader && !(leader == 0 && s == prev)) {
                int cnt = __popc(m);
                if (hib == 31) {                  // run extends past window
                    int j = b + 32;
                    while (j < M && idx[j] == s) {
                        float2 e2 = ((const float2*)emb)[j];
                        v += e2.x * e2.x + e2.y * e2.y;
                        ++cnt; ++j;
                    }
                }
                acc += __fdividef(v, (float)cnt);
            }
        }
        float wsum = warpsum(acc * hscale);
        if (lane == 0) bacc[warp] = wsum;
    } else {
        // ================= row role =================
        const int row = blockIdx.x * RPB + warp;
        float acc = 0.f;

        {
            RowS& S = sm[warp];

            for (int i = lane; i < NP1; i += 32) S.sd[i] = rsd[row * NP1 + i];
            __syncwarp();
            for (int i = lane; i < NV; i += 32) {
                float wv = rw[row * NV + i];
                S.wn[i] = wv * __fdividef(1.f, S.sd[i + 1] - S.sd[i] + 1e-8f);
            }

            if (lane < 3) {
                float d = pd[row * 3 + lane] - gt[row * 3 + lane];
                acc += d * d * (1.f / (3.f * 4096.f));
            }

            // ---- distortion via prefix sums (mid sorted; abs of nonneg sums = no-op) ----
            {
                float w0 = 0.f, w1 = 0.f, m0 = 0.f, m1 = 0.f, d0 = 0.f, d1 = 0.f;
                if (lane < 24) {
                    float2 wv = ((const float2*)(rw + row * NV))[lane];
                    w0 = wv.x; w1 = wv.y;
                    int n0 = 2 * lane;
                    float s0 = S.sd[n0], s1 = S.sd[n0 + 1], s2 = S.sd[n0 + 2];
                    m0 = 0.5f * (s0 + s1);
                    m1 = 0.5f * (s1 + s2);
                    d0 = s1 - s0;
                    d1 = s2 - s1;
                }
                float sw  = w0 + w1;
                float swm = w0 * m0 + w1 * m1;
                float cA = warp_excl_from_total(sw, lane);
                float cB = warp_excl_from_total(swm, lane);
                float p1 = 2.f * (w0 * (m0 * cA - cB)
                               + w1 * (m1 * (cA + w0) - (cB + w0 * m0)));
                float p2 = w0 * w0 * d0 + w1 * w1 * d1;
                acc += (p1 + p2 * (1.f / 3.f)) * (0.01f / 4096.f);
            }
            __syncwarp();

            #pragma unroll 1
            for (int lev = 0; lev < 2; ++lev) {
                const float pw = lev ? PW1 : PW0;
                const float inv2pw = lev ? (1.f / (2.f * PW1)) : (1.f / (2.f * PW0));
                const float* psd = lev ? psd1 : psd0;
                const float* pwt = lev ? pwt1 : pwt0;
                const int XP = lev ? XP1 : XP0;
                const float scale = 1.f / ((float)R * (float)(XP - 1));

                // ---- specialized stable merge (rank-scatter) ----
                {
                    const bool low1 = lane < 17;
                    const bool ok3  = lane < 2;
                    const int  j1   = low1 ? lane + 32 : lane - 17;
                    const int  j2   = lane + 15;
                    const int  j3   = lane + 47;

                    float val0 = S.sd[lane] - pw;
                    float val1 = low1 ? S.sd[j1] - pw : S.sd[j1] + pw;
                    float val2 = S.sd[j2] + pw;
                    float val3 = ok3 ? S.sd[j3] + pw : 0.f;

                    int lo0 = 0, hi0 = NP1, lo1 = 0, hi1 = NP1;
                    int lo2 = 0, hi2 = NP1, lo3 = 0, hi3 = NP1;
                    #pragma unroll
                    for (int s = 0; s < 6; ++s) {
                        if (lo0 < hi0) {
                            int mid = (lo0 + hi0) >> 1;
                            if (S.sd[mid] + pw < val0) lo0 = mid + 1; else hi0 = mid;
                        }
                        if (lo1 < hi1) {
                            int mid = (lo1 + hi1) >> 1;
                            float sv = S.sd[mid];
                            bool adv = low1 ? (sv + pw < val1) : (sv - pw <= val1);
                            if (adv) lo1 = mid + 1; else hi1 = mid;
                        }
                        if (lo2 < hi2) {
                            int mid = (lo2 + hi2) >> 1;
                            if (S.sd[mid] - pw <= val2) lo2 = mid + 1; else hi2 = mid;
                        }
                        if (ok3 && lo3 < hi3) {
                            int mid = (lo3 + hi3) >> 1;
                            if (S.sd[mid] - pw <= val3) lo3 = mid + 1; else hi3 = mid;
                        }
                    }
                    {
                        float dd = S.wn[lane] - (lane > 0 ? S.wn[lane - 1] : 0.f);
                        int pos = lane + lo0;
                        S.bounds[pos] = val0;
                        S.rs[pos] = dd * inv2pw;
                    }
                    {
                        float dd = (j1 < NV ? S.wn[j1] : 0.f) - (j1 > 0 ? S.wn[j1 - 1] : 0.f);
                        float rv = (low1 ? dd : -dd) * inv2pw;
                        int pos = j1 + lo1;
                        S.bounds[pos] = val1;
                        S.rs[pos] = rv;
                    }
                    {
                        float dd = S.wn[j2] - S.wn[j2 - 1];
                        int pos = j2 + lo2;
                        S.bounds[pos] = val2;
                        S.rs[pos] = -dd * inv2pw;
                    }
                    if (ok3) {
                        float dd = (j3 < NV ? S.wn[j3] : 0.f) - S.wn[j3 - 1];
                        int pos = j3 + lo3;
                        S.bounds[pos] = val3;
                        S.rs[pos] = -dd * inv2pw;
                    }
                    if (lane == 0) S.bounds[NB] = __int_as_float(0x7f800000); // +inf
                }
                __syncwarp();

                // three blocked scans over 97 elements
                const int base = lane * 4;
                float r4[4], ds4[4];
                #pragma unroll
                for (int t = 0; t < 4; ++t) {
                    int k = base + t;
                    bool v = (k < NB - 1);
                    r4[t]  = v ? S.rs[k] : 0.f;
                    ds4[t] = v ? (S.bounds[k + 1] - S.bounds[k]) : 0.f;
                }
                float c = 0.f, cum4[4];
                #pragma unroll
                for (int t = 0; t < 4; ++t) { c += r4[t]; cum4[t] = c; }
                float carry1 = warp_excl_from_total(c, lane);
                float c2 = 0.f, rec4[4];
                #pragma unroll
                for (int t = 0; t < 4; ++t) { c2 += ds4[t] * (cum4[t] + carry1); rec4[t] = c2; }
                float carry2 = warp_excl_from_total(c2, lane);
                float c3 = 0.f, cdf4[4], wb4[4];
                float wprev = (base == 0) ? 0.f : fmaxf(carry2, 0.f);
                #pragma unroll
                for (int t = 0; t < 4; ++t) {
                    float wbk1 = fmaxf(rec4[t] + carry2, 0.f);
                    wb4[t] = wbk1;
                    c3 += 0.5f * (wbk1 + wprev) * ds4[t];
                    cdf4[t] = c3;
                    wprev = wbk1;
                }
                float carry3 = warp_excl_from_total(c3, lane);
                #pragma unroll
                for (int t = 0; t < 4; ++t) {
                    int k = base + t;
                    if (k < NB - 1) {
                        S.wb[k + 1]  = wb4[t];
                        S.cdf[k + 1] = cdf4[t] + carry3;
                    }
                }
                if (lane == 0) { S.wb[0] = 0.f; S.cdf[0] = 0.f; }
                __syncwarp();

                // ---- build quadratic tables Bq/Gq directly ----
                // wbeq == wb on any equal-cdf run (all areas in the run are 0 with ds>0
                // => all wb in the run are exactly 0), so the first-of-run scan is dead.
                // Likewise cdf[k+1]==cdfN ties force wb[k+1]==0 for k<NB-2; for k==NB-2
                // the tie always holds => fp1 = 0 iff k >= NB-2.
                {
                    #pragma unroll
                    for (int t = 0; t < 4; ++t) {
                        int k = base + t;
                        if (k < NB) {
                            float wbk = S.wb[k];
                            if (k < NB - 1) {
                                float den  = S.bounds[k + 1] - S.bounds[k];
                                float fp1e = (k >= NB - 2) ? 0.f : S.wb[k + 1];
                                S.Bq[k] = wbk;
                                S.Gq[k] = 0.5f * (fp1e - wbk) * __fdividef(1.f, den);
                            } else {
                                S.Bq[k] = 0.5f * wbk;   // k = NB-1 tail: off = (num>0)
                                S.Gq[k] = 0.f;
                            }
                        }
                    }
                }
                __syncwarp();

                if (lev == 0) acc += interp_chunk<8>(S, psd, pwt, row, XP, lane, scale);
                else          acc += interp_chunk<3>(S, psd, pwt, row, XP, lane, scale);
                __syncwarp();
            }
        }

        float wa = warpsum(acc);
        if (lane == 0) bacc[warp] = wa;
    }

    // ===== tail: block sum -> global accum -> last block writes out =====
    __syncthreads();
    if (threadIdx.x == 0) {
        float t = 0.f;
        #pragma unroll
        for (int i = 0; i < RPB; ++i) t += bacc[i];
        atomicAdd(&g_accum, t);
        __threadfence();
        unsigned old = atomicAdd(&g_ctr, 1u);
        if (old == gridDim.x - 1) {
            float r = atomicExch(&g_accum, 0.f);
            out[0] = r;
            atomicExch(&g_ctr, 0u);
        }
    }
}

extern "C" void kernel_launch(void* const* d_in, const int* in_sizes, int n_in,
                              void* d_out, int out_size)
{
    const float* pd   = (const float*)d_in[0];
    const float* gt   = (const float*)d_in[1];
    const float* rsd  = (const float*)d_in[2];
    const float* rw   = (const float*)d_in[3];
    const float* psd0 = (const float*)d_in[4];
    const float* pwt0 = (const float*)d_in[5];
    const float* psd1 = (const float*)d_in[6];
    const float* pwt1 = (const float*)d_in[7];
    const float* emb0 = (const float*)d_in[8];
    const float* emb1 = (const float*)d_in[9];
    const int*   idx0 = (const int*)d_in[10];
    const int*   idx1 = (const int*)d_in[11];
    float* out = (float*)d_out;

    const int R   = in_sizes[0] / 3;
    const int XP0 = in_sizes[4] / R;
    const int XP1 = in_sizes[6] / R;
    const int M   = in_sizes[8] / 2;

    const int ROWB = (R + RPB - 1) / RPB;                        // 512
    const int HBL  = (M + RPB * 32 * HE - 1) / (RPB * 32 * HE);  // 96 per level

    mega_kernel<<<ROWB + 2 * HBL, RPB * 32>>>(pd, gt, rsd, rw,
                                              psd0, pwt0, psd1, pwt1,
                                              emb0, emb1, idx0, idx1,
                                              out, R, XP0, XP1, M, ROWB, HBL);
}

// round 17
// speedup vs baseline: 1.2058x; 1.0976x over previous
#include <cuda_runtime.h>

static constexpr int NV   = 48;
static constexpr int NP1  = 49;
static constexpr int NB   = 98;
static constexpr int NSEG = 65536;
static constexpr int RPB  = 8;     // rows per block (8 warps, 256 threads)
static constexpr int HE   = 8;     // hash windows per warp

static constexpr float PW0 = 0.01f;
static constexpr float PW1 = 0.005f;

// self-cleaning accumulator (zero-initialized; every launch restores 0/0)
__device__ float    g_accum = 0.f;
__device__ unsigned g_ctr   = 0u;

struct RowS {
    float sd[NP1];
    float wn[NV];
    float bounds[NB + 1];   // +1: sentinel = +inf
    float rs[NB];
    float wb[NB];           // wb[NB-1] stored pre-scaled by 0.5 (tail Bq)
    float cdf[NB];
    float Gq[NB];           // quadratic coeff
};

__device__ __forceinline__ float warpsum(float v) {
    #pragma unroll
    for (int o = 16; o; o >>= 1) v += __shfl_xor_sync(0xffffffffu, v, o);
    return v;
}

__device__ __forceinline__ float warp_excl_from_total(float tot, int lane) {
    float inc = tot;
    #pragma unroll
    for (int o = 1; o < 32; o <<= 1) {
        float y = __shfl_up_sync(0xffffffffu, inc, o);
        if (lane >= o) inc += y;
    }
    return inc - tot;
}

// interp: lane owns contiguous chunk of CH diffs; quadratic-table eval
// res(x) = cdf[k] + num*(wb[k] + num*Gq[k]),  num = x - bounds[k];  res = 0 for k<0
template <int CH>
__device__ __forceinline__ float interp_chunk(RowS& S, const float* __restrict__ psd,
                                              const float* __restrict__ pwt,
                                              int row, int XP, int lane, float scale)
{
    const int c0 = lane * CH;
    const float* px = psd + row * XP + c0;
    const float* pv = pwt + row * (XP - 1) + c0;

    float x = px[0];
    int lo = 0, hi = NB;
    #pragma unroll
    for (int st = 0; st < 7; ++st) {
        if (lo < hi) {
            int mid = (lo + hi) >> 1;
            if (S.bounds[mid] <= x) lo = mid + 1; else hi = mid;
        }
    }
    int k = lo - 1;
    float b0 = S.bounds[k < 0 ? 0 : k];
    float b1 = S.bounds[k + 1];          // bounds[NB] = +inf sentinel

    float lsum = 0.f, resprev = 0.f;
    #pragma unroll
    for (int j = 0; j <= CH; ++j) {
        if (j > 0) {
            x = px[j];
            while (b1 <= x) { ++k; b0 = b1; b1 = S.bounds[k + 1]; }
        }
        float res = 0.f;
        if (k >= 0) {
            float num = x - b0;
            res = fmaf(num, fmaf(num, S.Gq[k], S.wb[k]), S.cdf[k]);
        }
        if (j > 0) {
            float ws  = res - resprev;
            float pwv = pv[j - 1];
            float d = ws - pwv;
            if (d > 0.f) lsum += d * d * __fdividef(1.f, pwv + 1e-5f);
        }
        resprev = res;
    }
    return lsum * scale;
}

__global__ __launch_bounds__(RPB * 32)
void mega_kernel(const float* __restrict__ pd, const float* __restrict__ gt,
                 const float* __restrict__ rsd, const float* __restrict__ rw,
                 const float* __restrict__ psd0, const float* __restrict__ pwt0,
                 const float* __restrict__ psd1, const float* __restrict__ pwt1,
                 const float* __restrict__ emb0, const float* __restrict__ emb1,
                 const int* __restrict__ idx0, const int* __restrict__ idx1,
                 float* __restrict__ out, int R, int XP0, int XP1, int M,
                 int ROWB, int HBL)
{
    __shared__ RowS sm[RPB];
    __shared__ float bacc[RPB];

    const int warp = threadIdx.x >> 5;
    const int lane = threadIdx.x & 31;

    if (blockIdx.x >= (unsigned)ROWB) {
        // ================= hash role: run-ownership, no scratch =================
        int h     = blockIdx.x - ROWB;
        int level = h / HBL;
        int bh    = h % HBL;
        const float* emb = level ? emb1 : emb0;
        const int*   idx = level ? idx1 : idx0;
        const float hscale = 0.1f / (2.f * (float)NSEG);

        float acc = 0.f;
        const int warpbase = (bh * RPB + warp) * (32 * HE);
        #pragma unroll 1
        for (int e = 0; e < HE; ++e) {
            int b = warpbase + e * 32;
            if (b >= M) break;
            int i = b + lane;
            bool ok = i < M;
            int s = ok ? idx[i] : -1;
            float v = 0.f;
            if (ok) {
                float2 e2 = ((const float2*)emb)[i];
                v = e2.x * e2.x + e2.y * e2.y;
            }
            int prev = -2;
            if (lane == 0 && b > 0) prev = idx[b - 1];
            prev = __shfl_sync(0xffffffffu, prev, 0);

            unsigned m = __match_any_sync(0xffffffffu, s);
            int leader = __ffs(m) - 1;
            int hib = 31 - __clz(m);
            #pragma unroll
            for (int o = 16; o; o >>= 1) {
                float y = __shfl_down_sync(0xffffffffu, v, o);
                if (lane + o <= hib) v += y;
            }
            if (ok && lane == leader && !(leader == 0 && s == prev)) {
                int cnt = __popc(m);
                if (hib == 31) {                  // run extends past window
                    int j = b + 32;
                    while (j < M && idx[j] == s) {
                        float2 e2 = ((const float2*)emb)[j];
                        v += e2.x * e2.x + e2.y * e2.y;
                        ++cnt; ++j;
                    }
                }
                acc += __fdividef(v, (float)cnt);
            }
        }
        float wsum = warpsum(acc * hscale);
        if (lane == 0) bacc[warp] = wsum;
    } else {
        // ================= row role =================
        const int row = blockIdx.x * RPB + warp;
        float acc = 0.f;

        {
            RowS& S = sm[warp];

            for (int i = lane; i < NP1; i += 32) S.sd[i] = rsd[row * NP1 + i];
            __syncwarp();
            for (int i = lane; i < NV; i += 32) {
                float wv = rw[row * NV + i];
                S.wn[i] = wv * __fdividef(1.f, S.sd[i + 1] - S.sd[i] + 1e-8f);
            }

            if (lane < 3) {
                float d = pd[row * 3 + lane] - gt[row * 3 + lane];
                acc += d * d * (1.f / (3.f * 4096.f));
            }

            // ---- distortion via prefix sums (mid sorted; abs of nonneg sums = no-op) ----
            {
                float w0 = 0.f, w1 = 0.f, m0 = 0.f, m1 = 0.f, d0 = 0.f, d1 = 0.f;
                if (lane < 24) {
                    float2 wv = ((const float2*)(rw + row * NV))[lane];
                    w0 = wv.x; w1 = wv.y;
                    int n0 = 2 * lane;
                    float s0 = S.sd[n0], s1 = S.sd[n0 + 1], s2 = S.sd[n0 + 2];
                    m0 = 0.5f * (s0 + s1);
                    m1 = 0.5f * (s1 + s2);
                    d0 = s1 - s0;
                    d1 = s2 - s1;
                }
                float sw  = w0 + w1;
                float swm = w0 * m0 + w1 * m1;
                float cA = warp_excl_from_total(sw, lane);
                float cB = warp_excl_from_total(swm, lane);
                float p1 = 2.f * (w0 * (m0 * cA - cB)
                               + w1 * (m1 * (cA + w0) - (cB + w0 * m0)));
                float p2 = w0 * w0 * d0 + w1 * w1 * d1;
                acc += (p1 + p2 * (1.f / 3.f)) * (0.01f / 4096.f);
            }
            __syncwarp();

            #pragma unroll 1
            for (int lev = 0; lev < 2; ++lev) {
                const float pw = lev ? PW1 : PW0;
                const float inv2pw = lev ? (1.f / (2.f * PW1)) : (1.f / (2.f * PW0));
                const float* psd = lev ? psd1 : psd0;
                const float* pwt = lev ? pwt1 : pwt0;
                const int XP = lev ? XP1 : XP0;
                const float scale = 1.f / ((float)R * (float)(XP - 1));

                // ---- specialized stable merge (rank-scatter) ----
                {
                    const bool low1 = lane < 17;
                    const bool ok3  = lane < 2;
                    const int  j1   = low1 ? lane + 32 : lane - 17;
                    const int  j2   = lane + 15;
                    const int  j3   = lane + 47;

                    float val0 = S.sd[lane] - pw;
                    float val1 = low1 ? S.sd[j1] - pw : S.sd[j1] + pw;
                    float val2 = S.sd[j2] + pw;
                    float val3 = ok3 ? S.sd[j3] + pw : 0.f;

                    int lo0 = 0, hi0 = NP1, lo1 = 0, hi1 = NP1;
                    int lo2 = 0, hi2 = NP1, lo3 = 0, hi3 = NP1;
                    #pragma unroll
                    for (int s = 0; s < 6; ++s) {
                        if (lo0 < hi0) {
                            int mid = (lo0 + hi0) >> 1;
                            if (S.sd[mid] + pw < val0) lo0 = mid + 1; else hi0 = mid;
                        }
                        if (lo1 < hi1) {
                            int mid = (lo1 + hi1) >> 1;
                            float sv = S.sd[mid];
                            bool adv = low1 ? (sv + pw < val1) : (sv - pw <= val1);
                            if (adv) lo1 = mid + 1; else hi1 = mid;
                        }
                        if (lo2 < hi2) {
                            int mid = (lo2 + hi2) >> 1;
                            if (S.sd[mid] - pw <= val2) lo2 = mid + 1; else hi2 = mid;
                        }
                        if (ok3 && lo3 < hi3) {
                            int mid = (lo3 + hi3) >> 1;
                            if (S.sd[mid] - pw <= val3) lo3 = mid + 1; else hi3 = mid;
                        }
                    }
                    {
                        float dd = S.wn[lane] - (lane > 0 ? S.wn[lane - 1] : 0.f);
                        int pos = lane + lo0;
                        S.bounds[pos] = val0;
                        S.rs[pos] = dd * inv2pw;
                    }
                    {
                        float dd = (j1 < NV ? S.wn[j1] : 0.f) - (j1 > 0 ? S.wn[j1 - 1] : 0.f);
                        float rv = (low1 ? dd : -dd) * inv2pw;
                        int pos = j1 + lo1;
                        S.bounds[pos] = val1;
                        S.rs[pos] = rv;
                    }
                    {
                        float dd = S.wn[j2] - S.wn[j2 - 1];
                        int pos = j2 + lo2;
                        S.bounds[pos] = val2;
                        S.rs[pos] = -dd * inv2pw;
                    }
                    if (ok3) {
                        float dd = (j3 < NV ? S.wn[j3] : 0.f) - S.wn[j3 - 1];
                        int pos = j3 + lo3;
                        S.bounds[pos] = val3;
                        S.rs[pos] = -dd * inv2pw;
                    }
                    if (lane == 0) S.bounds[NB] = __int_as_float(0x7f800000); // +inf
                }
                __syncwarp();

                // ---- three blocked scans over 97 elements; Gq fused in epilogue ----
                const int base = lane * 4;
                float r4[4], ds4[4];
                #pragma unroll
                for (int t = 0; t < 4; ++t) {
                    int k = base + t;
                    bool v = (k < NB - 1);
                    r4[t]  = v ? S.rs[k] : 0.f;
                    ds4[t] = v ? (S.bounds[k + 1] - S.bounds[k]) : 0.f;
                }
                float c = 0.f, cum4[4];
                #pragma unroll
                for (int t = 0; t < 4; ++t) { c += r4[t]; cum4[t] = c; }
                float carry1 = warp_excl_from_total(c, lane);
                float c2 = 0.f, rec4[4];
                #pragma unroll
                for (int t = 0; t < 4; ++t) { c2 += ds4[t] * (cum4[t] + carry1); rec4[t] = c2; }
                float carry2 = warp_excl_from_total(c2, lane);
                float c3 = 0.f, cdf4[4], wb4[4], wprev4[4];
                float wprev = (base == 0) ? 0.f : fmaxf(carry2, 0.f);
                #pragma unroll
                for (int t = 0; t < 4; ++t) {
                    float wbk1 = fmaxf(rec4[t] + carry2, 0.f);
                    wb4[t] = wbk1;
                    wprev4[t] = wprev;              // == wb[base+t]
                    c3 += 0.5f * (wbk1 + wprev) * ds4[t];
                    cdf4[t] = c3;
                    wprev = wbk1;
                }
                float carry3 = warp_excl_from_total(c3, lane);
                #pragma unroll
                for (int t = 0; t < 4; ++t) {
                    int k = base + t;
                    if (k < NB - 1) {
                        // wb[NB-1] pre-scaled by 0.5 (tail linear coeff); unused elsewhere
                        S.wb[k + 1]  = (k == NB - 2) ? 0.5f * wb4[t] : wb4[t];
                        S.cdf[k + 1] = cdf4[t] + carry3;
                        float fp1e = (k >= NB - 2) ? 0.f : wb4[t];
                        S.Gq[k] = 0.5f * (fp1e - wprev4[t]) * __fdividef(1.f, ds4[t]);
                    } else if (k == NB - 1) {
                        S.Gq[k] = 0.f;
                    }
                }
                if (lane == 0) { S.wb[0] = 0.f; S.cdf[0] = 0.f; }
                __syncwarp();

                if (lev == 0) acc += interp_chunk<8>(S, psd, pwt, row, XP, lane, scale);
                else          acc += interp_chunk<3>(S, psd, pwt, row, XP, lane, scale);
                __syncwarp();
            }
        }

        float wa = warpsum(acc);
        if (lane == 0) bacc[warp] = wa;
    }

    // ===== tail: block sum -> global accum -> last block writes out =====
    __syncthreads();
    if (threadIdx.x == 0) {
        float t = 0.f;
        #pragma unroll
        for (int i = 0; i < RPB; ++i) t += bacc[i];
        atomicAdd(&g_accum, t);
        __threadfence();
        unsigned old = atomicAdd(&g_ctr, 1u);
        if (old == gridDim.x - 1) {
            float r = atomicExch(&g_accum, 0.f);
            out[0] = r;
            atomicExch(&g_ctr, 0u);
        }
    }
}

extern "C" void kernel_launch(void* const* d_in, const int* in_sizes, int n_in,
                              void* d_out, int out_size)
{
    const float* pd   = (const float*)d_in[0];
    const float* gt   = (const float*)d_in[1];
    const float* rsd  = (const float*)d_in[2];
    const float* rw   = (const float*)d_in[3];
    const float* psd0 = (const float*)d_in[4];
    const float* pwt0 = (const float*)d_in[5];
    const float* psd1 = (const float*)d_in[6];
    const float* pwt1 = (const float*)d_in[7];
    const float* emb0 = (const float*)d_in[8];
    const float* emb1 = (const float*)d_in[9];
    const int*   idx0 = (const int*)d_in[10];
    const int*   idx1 = (const int*)d_in[11];
    float* out = (float*)d_out;

    const int R   = in_sizes[0] / 3;
    const int XP0 = in_sizes[4] / R;
    const int XP1 = in_sizes[6] / R;
    const int M   = in_sizes[8] / 2;

    const int ROWB = (R + RPB - 1) / RPB;                        // 512
    const int HBL  = (M + RPB * 32 * HE - 1) / (RPB * 32 * HE);  // 96 per level

    mega_kernel<<<ROWB + 2 * HBL, RPB * 32>>>(pd, gt, rsd, rw,
                                              psd0, pwt0, psd1, pwt1,
                                              emb0, emb1, idx0, idx1,
                                              out, R, XP0, XP1, M, ROWB, HBL);
}